// round 6
// baseline (speedup 1.0000x reference)
#include <cuda_runtime.h>

#define SEQ 20
#define DK  64
#define BHB 2        // (b,h) problems per block
#define THREADS 256

#define QB 1300      // per-b float offset for sQ/sK (20*64=1280 +20 -> +5 bank-quads)
#define VS 68        // V smem row stride (float4-aligned)
#define WS 21        // raw scores smem row stride
#define TS 28        // transposed-W row stride (float4-aligned)

__global__ __launch_bounds__(THREADS, 5)
void sdpa_rel_kernel(const float* __restrict__ Qg,
                     const float* __restrict__ Kg,
                     const float* __restrict__ Vg,
                     const float* __restrict__ Mg,
                     float* __restrict__ deAtt,
                     float* __restrict__ attnOut)
{
    __shared__ __align__(16) float sQ[BHB * QB];
    __shared__ __align__(16) float sK[BHB * QB];
    __shared__ __align__(16) float sV[BHB][SEQ * VS];
    __shared__ float sS[BHB][SEQ * WS];
    __shared__ __align__(16) float sWt[BHB][SEQ * TS];   // W transposed: [k][q]
    __shared__ float sInv[BHB][SEQ];

    const int tid = threadIdx.x;
    const long bh0 = (long)blockIdx.x * BHB;

    // ---- Stage Q,K,V (coalesced float4 loads; swizzled float4 smem stores) ----
    for (int i = tid; i < BHB * (SEQ * DK / 4); i += THREADS) {
        int b   = i / (SEQ * DK / 4);
        int j   = i % (SEQ * DK / 4);
        int row = j / (DK / 4);
        int c4  = j % (DK / 4);
        const long base = (bh0 + b) * (long)(SEQ * DK);
        float4 q = ((const float4*)(Qg + base))[j];
        float4 k = ((const float4*)(Kg + base))[j];
        float4 v = ((const float4*)(Vg + base))[j];
        int sw = b * QB + row * DK + 4 * ((c4 + (row >> 2)) & 15);
        *((float4*)(sQ + sw)) = q;
        *((float4*)(sK + sw)) = k;
        *((float4*)(&sV[b][row * VS + 4 * c4])) = v;
    }
    __syncthreads();

    // ---- Phase A: S = Q K^T, 4x4 tiles, float4 swizzled loads (conflict-free) ----
    if (tid < BHB * 25) {
        int b    = tid / 25;
        int tile = tid % 25;
        int q0 = (tile / 5) * 4;
        int k0 = (tile % 5) * 4;
        const int sq = q0 >> 2;          // swizzle constant for the 4 q-rows
        const int sk = k0 >> 2;          // swizzle constant for the 4 k-rows
        const float* Qb = sQ + b * QB + q0 * DK;
        const float* Kb = sK + b * QB + k0 * DK;
        float acc[4][4] = {};
        #pragma unroll 4
        for (int d4 = 0; d4 < DK / 4; d4++) {
            int oq = 4 * ((d4 + sq) & 15);
            int ok = 4 * ((d4 + sk) & 15);
            float4 kv[4];
            #pragma unroll
            for (int j = 0; j < 4; j++)
                kv[j] = *((const float4*)(Kb + j * DK + ok));
            #pragma unroll
            for (int i = 0; i < 4; i++) {
                float4 qv = *((const float4*)(Qb + i * DK + oq));
                #pragma unroll
                for (int j = 0; j < 4; j++) {
                    acc[i][j] = fmaf(qv.x, kv[j].x, acc[i][j]);
                    acc[i][j] = fmaf(qv.y, kv[j].y, acc[i][j]);
                    acc[i][j] = fmaf(qv.z, kv[j].z, acc[i][j]);
                    acc[i][j] = fmaf(qv.w, kv[j].w, acc[i][j]);
                }
            }
        }
        #pragma unroll
        for (int i = 0; i < 4; i++)
            #pragma unroll
            for (int j = 0; j < 4; j++)
                sS[b][(q0 + i) * WS + (k0 + j)] = acc[i][j];
    }
    __syncthreads();

    // ---- exp(scale * S) * mask (mask read coalesced from global) ----
    for (int e = tid; e < BHB * SEQ * SEQ; e += THREADS) {
        int b = e / (SEQ * SEQ);
        int j = e % (SEQ * SEQ);
        int q = j / SEQ, k = j % SEQ;
        float raw = sS[b][q * WS + k];
        sS[b][q * WS + k] = __expf(raw * 0.125f) * Mg[(bh0 + b) * (long)(SEQ * SEQ) + j];
    }
    __syncthreads();

    // ---- row sums -> reciprocal ----
    if (tid < BHB * SEQ) {
        int b = tid / SEQ, q = tid % SEQ;
        float s = 0.f;
        #pragma unroll
        for (int k = 0; k < SEQ; k++) s += sS[b][q * WS + k];
        sInv[b][q] = 1.0f / (s + 1e-8f);
    }
    __syncthreads();

    // ---- normalize -> write attn; W = attn - |q-k| stored transposed ----
    for (int e = tid; e < BHB * SEQ * SEQ; e += THREADS) {
        int b = e / (SEQ * SEQ);
        int j = e % (SEQ * SEQ);
        int q = j / SEQ, k = j % SEQ;
        float a = sS[b][q * WS + k] * sInv[b][q];
        attnOut[(bh0 + b) * (long)(SEQ * SEQ) + j] = a;
        sWt[b][k * TS + q] = a - fabsf((float)(q - k));
    }
    __syncthreads();

    // ---- Phase C: deAtt = W @ V, 4q x 4d tiles, d0-major mapping ----
    if (tid < BHB * 80) {
        int b  = tid / 80;
        int t  = tid % 80;
        int d0 = (t / 5) * 4;
        int q0 = (t % 5) * 4;
        float4 acc[4];
        #pragma unroll
        for (int i = 0; i < 4; i++) acc[i] = make_float4(0.f, 0.f, 0.f, 0.f);
        #pragma unroll
        for (int k = 0; k < SEQ; k++) {
            float4 v = *((const float4*)(&sV[b][k * VS + d0]));
            float4 w = *((const float4*)(&sWt[b][k * TS + q0]));
            acc[0].x = fmaf(w.x, v.x, acc[0].x);
            acc[0].y = fmaf(w.x, v.y, acc[0].y);
            acc[0].z = fmaf(w.x, v.z, acc[0].z);
            acc[0].w = fmaf(w.x, v.w, acc[0].w);
            acc[1].x = fmaf(w.y, v.x, acc[1].x);
            acc[1].y = fmaf(w.y, v.y, acc[1].y);
            acc[1].z = fmaf(w.y, v.z, acc[1].z);
            acc[1].w = fmaf(w.y, v.w, acc[1].w);
            acc[2].x = fmaf(w.z, v.x, acc[2].x);
            acc[2].y = fmaf(w.z, v.y, acc[2].y);
            acc[2].z = fmaf(w.z, v.z, acc[2].z);
            acc[2].w = fmaf(w.z, v.w, acc[2].w);
            acc[3].x = fmaf(w.w, v.x, acc[3].x);
            acc[3].y = fmaf(w.w, v.y, acc[3].y);
            acc[3].z = fmaf(w.w, v.z, acc[3].z);
            acc[3].w = fmaf(w.w, v.w, acc[3].w);
        }
        const long base = (bh0 + b) * (long)(SEQ * DK);
        #pragma unroll
        for (int i = 0; i < 4; i++)
            *((float4*)(deAtt + base + (q0 + i) * DK + d0)) = acc[i];
    }
}

extern "C" void kernel_launch(void* const* d_in, const int* in_sizes, int n_in,
                              void* d_out, int out_size)
{
    const float* Q = (const float*)d_in[0];
    const float* K = (const float*)d_in[1];
    const float* V = (const float*)d_in[2];
    const float* M = (const float*)d_in[3];

    const int bh = in_sizes[0] / (SEQ * DK);   // 8192

    float* deAtt   = (float*)d_out;                      // [bh, SEQ, DK]
    float* attnOut = (float*)d_out + (long)in_sizes[0];  // [bh, SEQ, SEQ]

    const int grid = bh / BHB;                           // 4096
    sdpa_rel_kernel<<<grid, THREADS>>>(Q, K, V, M, deAtt, attnOut);
}

// round 7
// speedup vs baseline: 1.1511x; 1.1511x over previous
#include <cuda_runtime.h>

#define SEQ 20
#define DK  64
#define BHB 2
#define THREADS 256

#define QB 1280      // sQ/sK per-b floats (20 rows * 64, swizzled slots)
#define VB 1376      // sV per-b floats (row stride 68, padded to 128B multiple)
#define VR 68
#define WS 21        // sS row stride
#define WB 420       // sS per-b floats
#define TR 28        // sWt row stride
#define TB 576       // sWt per-b floats

__global__ __launch_bounds__(THREADS)
void sdpa_rel_kernel(const float* __restrict__ Qg,
                     const float* __restrict__ Kg,
                     const float* __restrict__ Vg,
                     const float* __restrict__ Mg,
                     float* __restrict__ deAtt,
                     float* __restrict__ attnOut)
{
    __shared__ __align__(16) float sQ[BHB * QB];
    __shared__ __align__(16) float sK[BHB * QB];
    __shared__ __align__(16) float sV[BHB * VB];
    __shared__ float sS[BHB * WB];
    __shared__ __align__(16) float sWt[BHB * TB];   // W transposed: [k][q]

    const int tid  = threadIdx.x;
    const int wid  = tid >> 5;
    const int lane = tid & 31;
    const long bh0 = (long)blockIdx.x * BHB;

    // ---- prefetch mask into registers BEFORE any barrier (hides DRAM lat) ----
    float4 m4;
    if (tid < 200)
        m4 = ((const float4*)Mg)[bh0 * 100 + tid];

    // ---- Stage Q,K,V: coalesced float4 loads, swizzled float4 smem stores ----
    #pragma unroll
    for (int r = 0; r < 3; r++) {
        int i = tid + r * THREADS;
        if (i < BHB * (SEQ * DK / 4)) {
            int b   = i / (SEQ * DK / 4);
            int j   = i % (SEQ * DK / 4);
            int row = j / (DK / 4);
            int c4  = j % (DK / 4);
            const long base4 = (bh0 + b) * (long)(SEQ * DK / 4);
            float4 q = ((const float4*)Qg)[base4 + j];
            float4 k = ((const float4*)Kg)[base4 + j];
            float4 v = ((const float4*)Vg)[base4 + j];
            int sw = b * QB + row * DK + 4 * ((c4 + (row >> 2)) & 15);
            *((float4*)(sQ + sw)) = q;
            *((float4*)(sK + sw)) = k;
            *((float4*)(sV + b * VB + row * VR + 4 * c4)) = v;
        }
    }
    __syncthreads();

    // ---- Phase A: S = Q K^T, 4x4 tiles; one warp per b (warps 6,7) ----
    if (wid >= 6 && lane < 25) {
        const int b  = wid - 6;
        const int q0 = (lane / 5) * 4;
        const int k0 = (lane % 5) * 4;
        const int dks = ((k0 >> 2) - (q0 >> 2)) & 15;
        const float* Qb = sQ + b * QB + q0 * DK;
        const float* Kb = sK + b * QB + k0 * DK;
        float acc[4][4] = {};
        #pragma unroll
        for (int s = 0; s < 16; s++) {           // physical Q slot (compile-time offset)
            const int ok = 4 * ((s + dks) & 15); // matching K slot
            float4 kv[4];
            #pragma unroll
            for (int j = 0; j < 4; j++)
                kv[j] = *((const float4*)(Kb + j * DK + ok));
            #pragma unroll
            for (int i = 0; i < 4; i++) {
                float4 qv = *((const float4*)(Qb + i * DK + 4 * s));
                #pragma unroll
                for (int j = 0; j < 4; j++) {
                    acc[i][j] = fmaf(qv.x, kv[j].x, acc[i][j]);
                    acc[i][j] = fmaf(qv.y, kv[j].y, acc[i][j]);
                    acc[i][j] = fmaf(qv.z, kv[j].z, acc[i][j]);
                    acc[i][j] = fmaf(qv.w, kv[j].w, acc[i][j]);
                }
            }
        }
        #pragma unroll
        for (int i = 0; i < 4; i++)
            #pragma unroll
            for (int j = 0; j < 4; j++)
                sS[b * WB + (q0 + i) * WS + (k0 + j)] = acc[i][j];
    }
    __syncthreads();

    // ---- exp(scale*S) * mask, mask already in registers (threads 0-199) ----
    if (tid < 200) {
        int e = 4 * tid;
        int b = tid / 100;
        int j = e % (SEQ * SEQ);
        int q = j / SEQ, k = j % SEQ;
        float* p = sS + b * WB + q * WS + k;
        p[0] = __expf(p[0] * 0.125f) * m4.x;
        p[1] = __expf(p[1] * 0.125f) * m4.y;
        p[2] = __expf(p[2] * 0.125f) * m4.z;
        p[3] = __expf(p[3] * 0.125f) * m4.w;
    }
    __syncthreads();

    // ---- row phase (warps 4,5): sum, normalize, write attn, build W^T ----
    if (wid >= 4 && wid < 6 && lane < SEQ) {
        const int b = wid - 4;
        const int q = lane;
        const float* row = sS + b * WB + q * WS;
        float s = 0.f;
        #pragma unroll
        for (int k = 0; k < SEQ; k++) s += row[k];
        const float inv = 1.0f / (s + 1e-8f);
        float4* Arow = (float4*)(attnOut + (bh0 + b) * (long)(SEQ * SEQ) + q * SEQ);
        #pragma unroll
        for (int k4 = 0; k4 < SEQ / 4; k4++) {
            float a0 = row[k4 * 4 + 0] * inv;
            float a1 = row[k4 * 4 + 1] * inv;
            float a2 = row[k4 * 4 + 2] * inv;
            float a3 = row[k4 * 4 + 3] * inv;
            Arow[k4] = make_float4(a0, a1, a2, a3);
            sWt[b * TB + (k4 * 4 + 0) * TR + q] = a0 - fabsf((float)(q - (k4 * 4 + 0)));
            sWt[b * TB + (k4 * 4 + 1) * TR + q] = a1 - fabsf((float)(q - (k4 * 4 + 1)));
            sWt[b * TB + (k4 * 4 + 2) * TR + q] = a2 - fabsf((float)(q - (k4 * 4 + 2)));
            sWt[b * TB + (k4 * 4 + 3) * TR + q] = a3 - fabsf((float)(q - (k4 * 4 + 3)));
        }
    }
    __syncthreads();

    // ---- Phase C: deAtt = W @ V, 4q x 4d tiles, d0-major (warps 0-4) ----
    if (tid < BHB * 80) {
        const int b  = tid / 80;
        const int t  = tid % 80;
        const int d0 = (t / 5) * 4;
        const int q0 = (t % 5) * 4;
        const float* Vb = sV + b * VB + d0;
        const float* Wb = sWt + b * TB + q0;
        float4 acc[4];
        #pragma unroll
        for (int i = 0; i < 4; i++) acc[i] = make_float4(0.f, 0.f, 0.f, 0.f);
        #pragma unroll
        for (int k = 0; k < SEQ; k++) {
            float4 v = *((const float4*)(Vb + k * VR));
            float4 w = *((const float4*)(Wb + k * TR));
            acc[0].x = fmaf(w.x, v.x, acc[0].x);
            acc[0].y = fmaf(w.x, v.y, acc[0].y);
            acc[0].z = fmaf(w.x, v.z, acc[0].z);
            acc[0].w = fmaf(w.x, v.w, acc[0].w);
            acc[1].x = fmaf(w.y, v.x, acc[1].x);
            acc[1].y = fmaf(w.y, v.y, acc[1].y);
            acc[1].z = fmaf(w.y, v.z, acc[1].z);
            acc[1].w = fmaf(w.y, v.w, acc[1].w);
            acc[2].x = fmaf(w.z, v.x, acc[2].x);
            acc[2].y = fmaf(w.z, v.y, acc[2].y);
            acc[2].z = fmaf(w.z, v.z, acc[2].z);
            acc[2].w = fmaf(w.z, v.w, acc[2].w);
            acc[3].x = fmaf(w.w, v.x, acc[3].x);
            acc[3].y = fmaf(w.w, v.y, acc[3].y);
            acc[3].z = fmaf(w.w, v.z, acc[3].z);
            acc[3].w = fmaf(w.w, v.w, acc[3].w);
        }
        const long base = (bh0 + b) * (long)(SEQ * DK);
        #pragma unroll
        for (int i = 0; i < 4; i++)
            *((float4*)(deAtt + base + (q0 + i) * DK + d0)) = acc[i];
    }
}

extern "C" void kernel_launch(void* const* d_in, const int* in_sizes, int n_in,
                              void* d_out, int out_size)
{
    const float* Q = (const float*)d_in[0];
    const float* K = (const float*)d_in[1];
    const float* V = (const float*)d_in[2];
    const float* M = (const float*)d_in[3];

    const int bh = in_sizes[0] / (SEQ * DK);   // 8192

    float* deAtt   = (float*)d_out;                      // [bh, SEQ, DK]
    float* attnOut = (float*)d_out + (long)in_sizes[0];  // [bh, SEQ, SEQ]

    const int grid = bh / BHB;                           // 4096
    sdpa_rel_kernel<<<grid, THREADS>>>(Q, K, V, M, deAtt, attnOut);
}

// round 9
// speedup vs baseline: 1.1843x; 1.0288x over previous
#include <cuda_runtime.h>
#include <cstdint>

#define SEQ 20
#define DK  64
#define ITERS 8
#define THREADS 128

#define RS 68                 // Q,K,V smem row stride (272B: shifts bank by 1 quad/row)
#define WS 20                 // sS row stride (float4-aligned)
#define TR 28                 // sWt row stride

// per-buffer float offsets
#define OQ 0
#define OK 1360
#define OV 2720
#define OM 4080               // mask, 400 floats linear [q*20+k]
#define BUFB 4480             // floats per buffer (17920B, 16B-aligned)

__device__ __forceinline__ void cp16(unsigned int saddr, const void* g) {
    asm volatile("cp.async.cg.shared.global [%0], [%1], 16;" :: "r"(saddr), "l"(g));
}

__device__ __forceinline__ void issue_loads(const float4* __restrict__ Q4,
                                            const float4* __restrict__ K4,
                                            const float4* __restrict__ V4,
                                            const float4* __restrict__ M4,
                                            long bh, float* buf, int tid)
{
    unsigned int sb = (unsigned int)__cvta_generic_to_shared(buf);
    const float4* q = Q4 + bh * 320;
    const float4* k = K4 + bh * 320;
    const float4* v = V4 + bh * 320;
    #pragma unroll
    for (int r = 0; r < 3; r++) {
        int i = tid + r * THREADS;
        if (i < 320) {
            int row = i >> 4, c4 = i & 15;
            unsigned int off = (unsigned int)(row * RS + 4 * c4) * 4u;
            cp16(sb + (OQ * 4u) + off, q + i);
            cp16(sb + (OK * 4u) + off, k + i);
            cp16(sb + (OV * 4u) + off, v + i);
        }
    }
    if (tid < 100)
        cp16(sb + (OM + 4 * tid) * 4u, M4 + bh * 100 + tid);
}

__global__ __launch_bounds__(THREADS)
void sdpa_rel_kernel(const float* __restrict__ Qg,
                     const float* __restrict__ Kg,
                     const float* __restrict__ Vg,
                     const float* __restrict__ Mg,
                     float* __restrict__ deAtt,
                     float* __restrict__ attnOut)
{
    __shared__ __align__(16) float sBuf[2 * BUFB];
    __shared__ __align__(16) float sS[SEQ * WS];
    __shared__ float sWt[19 * TR + SEQ];          // W transposed: [k*TR + q]

    const int tid  = threadIdx.x;
    const int wid  = tid >> 5;
    const int lane = tid & 31;
    const long bhBase = (long)blockIdx.x * ITERS;

    const float4* Q4 = (const float4*)Qg;
    const float4* K4 = (const float4*)Kg;
    const float4* V4 = (const float4*)Vg;
    const float4* M4 = (const float4*)Mg;

    // prologue: stage iteration 0
    issue_loads(Q4, K4, V4, M4, bhBase, sBuf, tid);
    asm volatile("cp.async.commit_group;" ::: "memory");

    for (int it = 0; it < ITERS; it++) {
        const long bh = bhBase + it;
        float* buf = sBuf + (it & 1) * BUFB;

        if (it + 1 < ITERS) {
            issue_loads(Q4, K4, V4, M4, bh + 1, sBuf + ((it + 1) & 1) * BUFB, tid);
            asm volatile("cp.async.commit_group;" ::: "memory");
            asm volatile("cp.async.wait_group 1;" ::: "memory");
        } else {
            asm volatile("cp.async.wait_group 0;" ::: "memory");
        }
        __syncthreads();   // buf[it] ready for everyone

        const int vw = (wid + it) & 3;   // rotate roles across SMSPs per iteration

        // ---- Phase A: S = Q K^T, 4x4 tiles, one warp (vw==3) ----
        if (vw == 3 && lane < 25) {
            const int q0 = (lane / 5) * 4;
            const int k0 = (lane % 5) * 4;
            const float* Qb = buf + OQ + q0 * RS;
            const float* Kb = buf + OK + k0 * RS;
            float acc[4][4] = {};
            #pragma unroll
            for (int d4 = 0; d4 < DK / 4; d4++) {
                float4 kv[4];
                #pragma unroll
                for (int j = 0; j < 4; j++)
                    kv[j] = *((const float4*)(Kb + j * RS + 4 * d4));
                #pragma unroll
                for (int i = 0; i < 4; i++) {
                    float4 qv = *((const float4*)(Qb + i * RS + 4 * d4));
                    #pragma unroll
                    for (int j = 0; j < 4; j++) {
                        acc[i][j] = fmaf(qv.x, kv[j].x, acc[i][j]);
                        acc[i][j] = fmaf(qv.y, kv[j].y, acc[i][j]);
                        acc[i][j] = fmaf(qv.z, kv[j].z, acc[i][j]);
                        acc[i][j] = fmaf(qv.w, kv[j].w, acc[i][j]);
                    }
                }
            }
            #pragma unroll
            for (int i = 0; i < 4; i++)
                #pragma unroll
                for (int j = 0; j < 4; j++)
                    sS[(q0 + i) * WS + (k0 + j)] = acc[i][j];
        }
        __syncthreads();

        // ---- Row phase (vw==2): exp*mask, sum, normalize, attn out, W^T ----
        if (vw == 2 && lane < SEQ) {
            const int q = lane;
            const float4* srow = (const float4*)(sS + q * WS);
            const float4* mrow = (const float4*)(buf + OM + q * SEQ);
            float w[SEQ];
            float sum = 0.f;
            #pragma unroll
            for (int k4 = 0; k4 < SEQ / 4; k4++) {
                float4 sv = srow[k4];
                float4 mv = mrow[k4];
                w[k4 * 4 + 0] = __expf(sv.x * 0.125f) * mv.x;
                w[k4 * 4 + 1] = __expf(sv.y * 0.125f) * mv.y;
                w[k4 * 4 + 2] = __expf(sv.z * 0.125f) * mv.z;
                w[k4 * 4 + 3] = __expf(sv.w * 0.125f) * mv.w;
                sum += w[k4 * 4 + 0] + w[k4 * 4 + 1] + w[k4 * 4 + 2] + w[k4 * 4 + 3];
            }
            const float inv = 1.0f / (sum + 1e-8f);
            float4* Arow = (float4*)(attnOut + bh * (long)(SEQ * SEQ) + q * SEQ);
            #pragma unroll
            for (int k4 = 0; k4 < SEQ / 4; k4++) {
                float a0 = w[k4 * 4 + 0] * inv;
                float a1 = w[k4 * 4 + 1] * inv;
                float a2 = w[k4 * 4 + 2] * inv;
                float a3 = w[k4 * 4 + 3] * inv;
                Arow[k4] = make_float4(a0, a1, a2, a3);
                sWt[(k4 * 4 + 0) * TR + q] = a0 - fabsf((float)(q - (k4 * 4 + 0)));
                sWt[(k4 * 4 + 1) * TR + q] = a1 - fabsf((float)(q - (k4 * 4 + 1)));
                sWt[(k4 * 4 + 2) * TR + q] = a2 - fabsf((float)(q - (k4 * 4 + 2)));
                sWt[(k4 * 4 + 3) * TR + q] = a3 - fabsf((float)(q - (k4 * 4 + 3)));
            }
        }
        __syncthreads();

        // ---- Phase C: deAtt = W @ V, 4q x 4d tiles (vt<80, d-major) ----
        {
            const int vt = vw * 32 + lane;
            if (vt < 80) {
                const int d0 = 4 * (vt & 15);
                const int q0 = 4 * (vt >> 4);
                const float* Vb = buf + OV + d0;
                const float* Wb = sWt + q0;
                float4 acc[4];
                #pragma unroll
                for (int i = 0; i < 4; i++) acc[i] = make_float4(0.f, 0.f, 0.f, 0.f);
                #pragma unroll
                for (int k = 0; k < SEQ; k++) {
                    float4 v = *((const float4*)(Vb + k * RS));
                    float4 w = *((const float4*)(Wb + k * TR));
                    acc[0].x = fmaf(w.x, v.x, acc[0].x);
                    acc[0].y = fmaf(w.x, v.y, acc[0].y);
                    acc[0].z = fmaf(w.x, v.z, acc[0].z);
                    acc[0].w = fmaf(w.x, v.w, acc[0].w);
                    acc[1].x = fmaf(w.y, v.x, acc[1].x);
                    acc[1].y = fmaf(w.y, v.y, acc[1].y);
                    acc[1].z = fmaf(w.y, v.z, acc[1].z);
                    acc[1].w = fmaf(w.y, v.w, acc[1].w);
                    acc[2].x = fmaf(w.z, v.x, acc[2].x);
                    acc[2].y = fmaf(w.z, v.y, acc[2].y);
                    acc[2].z = fmaf(w.z, v.z, acc[2].z);
                    acc[2].w = fmaf(w.z, v.w, acc[2].w);
                    acc[3].x = fmaf(w.w, v.x, acc[3].x);
                    acc[3].y = fmaf(w.w, v.y, acc[3].y);
                    acc[3].z = fmaf(w.w, v.z, acc[3].z);
                    acc[3].w = fmaf(w.w, v.w, acc[3].w);
                }
                const long base = bh * (long)(SEQ * DK);
                #pragma unroll
                for (int i = 0; i < 4; i++)
                    *((float4*)(deAtt + base + (q0 + i) * DK + d0)) = acc[i];
            }
        }
        __syncthreads();   // end of iteration: buf/sS/sWt safe to reuse
    }
}

extern "C" void kernel_launch(void* const* d_in, const int* in_sizes, int n_in,
                              void* d_out, int out_size)
{
    const float* Q = (const float*)d_in[0];
    const float* K = (const float*)d_in[1];
    const float* V = (const float*)d_in[2];
    const float* M = (const float*)d_in[3];

    const int bh = in_sizes[0] / (SEQ * DK);   // 8192

    float* deAtt   = (float*)d_out;                      // [bh, SEQ, DK]
    float* attnOut = (float*)d_out + (long)in_sizes[0];  // [bh, SEQ, SEQ]

    const int grid = bh / ITERS;                         // 1024
    sdpa_rel_kernel<<<grid, THREADS>>>(Q, K, V, M, deAtt, attnOut);
}

// round 10
// speedup vs baseline: 1.2735x; 1.0753x over previous
#include <cuda_runtime.h>
#include <cstdint>

#define SEQ 20
#define DK  64
#define THREADS 128
#define GRID 740              // 5 blocks/SM * 148 SMs: persistent, tail-free

#define RS 68                 // Q,K,V smem row stride
#define TR 28                 // sWt row stride (S^T / W^T buffer)

// per-buffer float offsets
#define OQ 0
#define OK 1360
#define OV 2720
#define OM 4080               // mask, 400 floats [q*20+k]
#define BUFB 4480             // floats per buffer

typedef unsigned long long ull;

__device__ __forceinline__ ull fma2(ull a, ull b, ull c) {
    ull d;
    asm("fma.rn.f32x2 %0, %1, %2, %3;" : "=l"(d) : "l"(a), "l"(b), "l"(c));
    return d;
}
__device__ __forceinline__ float lohi(ull v) {
    float2 r;
    asm("mov.b64 {%0, %1}, %2;" : "=f"(r.x), "=f"(r.y) : "l"(v));
    return r.x + r.y;
}

__device__ __forceinline__ void cp16(unsigned int saddr, const void* g) {
    asm volatile("cp.async.cg.shared.global [%0], [%1], 16;" :: "r"(saddr), "l"(g));
}

__device__ __forceinline__ void issue_loads(const float4* __restrict__ Q4,
                                            const float4* __restrict__ K4,
                                            const float4* __restrict__ V4,
                                            const float4* __restrict__ M4,
                                            long bh, float* buf, int tid)
{
    unsigned int sb = (unsigned int)__cvta_generic_to_shared(buf);
    const float4* q = Q4 + bh * 320;
    const float4* k = K4 + bh * 320;
    const float4* v = V4 + bh * 320;
    #pragma unroll
    for (int r = 0; r < 3; r++) {
        int i = tid + r * THREADS;
        if (i < 320) {
            int row = i >> 4, c4 = i & 15;
            unsigned int off = (unsigned int)(row * RS + 4 * c4) * 4u;
            cp16(sb + (OQ * 4u) + off, q + i);
            cp16(sb + (OK * 4u) + off, k + i);
            cp16(sb + (OV * 4u) + off, v + i);
        }
    }
    if (tid < 100)
        cp16(sb + (OM + 4 * tid) * 4u, M4 + bh * 100 + tid);
}

__global__ __launch_bounds__(THREADS)
void sdpa_rel_kernel(const float* __restrict__ Qg,
                     const float* __restrict__ Kg,
                     const float* __restrict__ Vg,
                     const float* __restrict__ Mg,
                     float* __restrict__ deAtt,
                     float* __restrict__ attnOut,
                     int total)
{
    __shared__ __align__(16) float sBuf[2 * BUFB];
    __shared__ __align__(16) float sWt[SEQ * TR];   // S^T then W^T: [k*TR + q]

    const int tid  = threadIdx.x;
    const int wid  = tid >> 5;
    const int lane = tid & 31;
    const int G    = gridDim.x;

    const float4* Q4 = (const float4*)Qg;
    const float4* K4 = (const float4*)Kg;
    const float4* V4 = (const float4*)Vg;
    const float4* M4 = (const float4*)Mg;

    // prologue: stage first problem
    issue_loads(Q4, K4, V4, M4, blockIdx.x, sBuf, tid);
    asm volatile("cp.async.commit_group;" ::: "memory");

    int it = 0;
    for (long bh = blockIdx.x; bh < total; bh += G, it++) {
        float* buf = sBuf + (it & 1) * BUFB;

        if (bh + G < total) {
            issue_loads(Q4, K4, V4, M4, bh + G, sBuf + ((it + 1) & 1) * BUFB, tid);
            asm volatile("cp.async.commit_group;" ::: "memory");
            asm volatile("cp.async.wait_group 1;" ::: "memory");
        } else {
            asm volatile("cp.async.wait_group 0;" ::: "memory");
        }
        __syncthreads();   // current buffer ready for all

        // ---- Phase A: S^T = (Q K^T)^T, 2q x 2k tiles, f32x2, 100 lanes ----
        if (tid < 100) {
            const int q0 = (tid / 10) * 2;
            const int k0 = (tid % 10) * 2;
            const float* Qb = buf + OQ + q0 * RS;
            const float* Kb = buf + OK + k0 * RS;
            ull a00 = 0ull, a01 = 0ull, a10 = 0ull, a11 = 0ull;
            #pragma unroll
            for (int d4 = 0; d4 < DK / 4; d4++) {
                ulonglong2 Q0 = *(const ulonglong2*)(Qb + 4 * d4);
                ulonglong2 Q1 = *(const ulonglong2*)(Qb + RS + 4 * d4);
                ulonglong2 K0 = *(const ulonglong2*)(Kb + 4 * d4);
                ulonglong2 K1 = *(const ulonglong2*)(Kb + RS + 4 * d4);
                a00 = fma2(Q0.x, K0.x, a00);
                a01 = fma2(Q0.x, K1.x, a01);
                a10 = fma2(Q1.x, K0.x, a10);
                a11 = fma2(Q1.x, K1.x, a11);
                a00 = fma2(Q0.y, K0.y, a00);
                a01 = fma2(Q0.y, K1.y, a01);
                a10 = fma2(Q1.y, K0.y, a10);
                a11 = fma2(Q1.y, K1.y, a11);
            }
            sWt[k0 * TR + q0]             = lohi(a00);
            sWt[(k0 + 1) * TR + q0]       = lohi(a01);
            sWt[k0 * TR + q0 + 1]         = lohi(a10);
            sWt[(k0 + 1) * TR + q0 + 1]   = lohi(a11);
        }
        __syncthreads();

        // ---- Row phase (warp 3): exp*mask, sum, normalize, attn out, W^T in place ----
        if (wid == 3 && lane < SEQ) {
            const int q = lane;
            const float4* mrow = (const float4*)(buf + OM + q * SEQ);
            float w[SEQ];
            float sum = 0.f;
            #pragma unroll
            for (int k4 = 0; k4 < SEQ / 4; k4++) {
                float4 mv = mrow[k4];
                w[k4 * 4 + 0] = __expf(sWt[(k4 * 4 + 0) * TR + q] * 0.125f) * mv.x;
                w[k4 * 4 + 1] = __expf(sWt[(k4 * 4 + 1) * TR + q] * 0.125f) * mv.y;
                w[k4 * 4 + 2] = __expf(sWt[(k4 * 4 + 2) * TR + q] * 0.125f) * mv.z;
                w[k4 * 4 + 3] = __expf(sWt[(k4 * 4 + 3) * TR + q] * 0.125f) * mv.w;
                sum += w[k4 * 4 + 0] + w[k4 * 4 + 1] + w[k4 * 4 + 2] + w[k4 * 4 + 3];
            }
            const float inv = 1.0f / (sum + 1e-8f);
            float4* Arow = (float4*)(attnOut + bh * (long)(SEQ * SEQ) + q * SEQ);
            #pragma unroll
            for (int k4 = 0; k4 < SEQ / 4; k4++) {
                float a0 = w[k4 * 4 + 0] * inv;
                float a1 = w[k4 * 4 + 1] * inv;
                float a2 = w[k4 * 4 + 2] * inv;
                float a3 = w[k4 * 4 + 3] * inv;
                Arow[k4] = make_float4(a0, a1, a2, a3);
                sWt[(k4 * 4 + 0) * TR + q] = a0 - fabsf((float)(q - (k4 * 4 + 0)));
                sWt[(k4 * 4 + 1) * TR + q] = a1 - fabsf((float)(q - (k4 * 4 + 1)));
                sWt[(k4 * 4 + 2) * TR + q] = a2 - fabsf((float)(q - (k4 * 4 + 2)));
                sWt[(k4 * 4 + 3) * TR + q] = a3 - fabsf((float)(q - (k4 * 4 + 3)));
            }
        }
        __syncthreads();

        // ---- Phase C: deAtt = W @ V, 4q x 4d tiles, 80 lanes, d-major ----
        if (tid < 80) {
            const int d0 = 4 * (tid & 15);
            const int q0 = 4 * (tid >> 4);
            const float* Vb = buf + OV + d0;
            const float* Wb = sWt + q0;
            float4 acc[4];
            #pragma unroll
            for (int i = 0; i < 4; i++) acc[i] = make_float4(0.f, 0.f, 0.f, 0.f);
            #pragma unroll
            for (int k = 0; k < SEQ; k++) {
                float4 v = *((const float4*)(Vb + k * RS));
                float4 w = *((const float4*)(Wb + k * TR));
                acc[0].x = fmaf(w.x, v.x, acc[0].x);
                acc[0].y = fmaf(w.x, v.y, acc[0].y);
                acc[0].z = fmaf(w.x, v.z, acc[0].z);
                acc[0].w = fmaf(w.x, v.w, acc[0].w);
                acc[1].x = fmaf(w.y, v.x, acc[1].x);
                acc[1].y = fmaf(w.y, v.y, acc[1].y);
                acc[1].z = fmaf(w.y, v.z, acc[1].z);
                acc[1].w = fmaf(w.y, v.w, acc[1].w);
                acc[2].x = fmaf(w.z, v.x, acc[2].x);
                acc[2].y = fmaf(w.z, v.y, acc[2].y);
                acc[2].z = fmaf(w.z, v.z, acc[2].z);
                acc[2].w = fmaf(w.z, v.w, acc[2].w);
                acc[3].x = fmaf(w.w, v.x, acc[3].x);
                acc[3].y = fmaf(w.w, v.y, acc[3].y);
                acc[3].z = fmaf(w.w, v.z, acc[3].z);
                acc[3].w = fmaf(w.w, v.w, acc[3].w);
            }
            const long base = bh * (long)(SEQ * DK);
            #pragma unroll
            for (int i = 0; i < 4; i++)
                *((float4*)(deAtt + base + (q0 + i) * DK + d0)) = acc[i];
        }
        __syncthreads();   // sWt/buf reuse fence
    }
}

extern "C" void kernel_launch(void* const* d_in, const int* in_sizes, int n_in,
                              void* d_out, int out_size)
{
    const float* Q = (const float*)d_in[0];
    const float* K = (const float*)d_in[1];
    const float* V = (const float*)d_in[2];
    const float* M = (const float*)d_in[3];

    const int total = in_sizes[0] / (SEQ * DK);          // 8192

    float* deAtt   = (float*)d_out;                      // [bh, SEQ, DK]
    float* attnOut = (float*)d_out + (long)in_sizes[0];  // [bh, SEQ, SEQ]

    const int grid = (total < GRID) ? total : GRID;
    sdpa_rel_kernel<<<grid, THREADS>>>(Q, K, V, M, deAtt, attnOut, total);
}